// round 8
// baseline (speedup 1.0000x reference)
#include <cuda_runtime.h>
#include <math.h>

#define B_  32
#define H_  56
#define W_  56
#define C_  256
#define NROWS (B_ * H_)          // 1792
#define ROW_F4 (W_ * C_ / 4)     // 3584 float4 per row

// Cross-CTA handshake state (zero-initialized once; reset inside each launch).
__device__ float2 g_pooled[NROWS * W_];
__device__ int    g_flag[NROWS];
__device__ int    g_done[NROWS];

// Dynamic SMEM layout:
//   float4 xrow[3584]         57344 B
//   float2 pool7[7*56]         3136 B
//   float  attn[56]             224 B
//   float  w[98]                392 B
#define SMEM_BYTES 61440

__global__ __launch_bounds__(256) void fused_kernel(
    const float* __restrict__ x,
    const float* __restrict__ conv_w,   // [7][7][2] HWIO
    const float* __restrict__ conv_b,   // [1]
    float* __restrict__ out)
{
    extern __shared__ float4 smem[];
    float4* xrow  = smem;                                // [3584]
    float2* pool7 = (float2*)(smem + ROW_F4);            // [7][56]
    float*  s_attn = (float*)(pool7 + 7 * W_);           // [56]
    float*  s_w    = s_attn + W_;                        // [98]

    const int tid = threadIdx.x;
    const int bh  = blockIdx.x;        // b*H_ + h
    const int b   = bh / H_;
    const int h   = bh % H_;

    if (tid < 98) s_w[tid] = conv_w[tid];

    // ---- Phase 1: load this row of x into SMEM (read x from DRAM exactly once)
    const size_t row_base4 = (size_t)bh * ROW_F4;
    const float4* __restrict__ x4 = reinterpret_cast<const float4*>(x) + row_base4;
    #pragma unroll
    for (int it = 0; it < 14; it++) {
        const int idx = it * 256 + tid;
        xrow[idx] = x4[idx];
    }
    __syncthreads();

    // ---- Phase 2: per-pixel channel avg/max from SMEM, publish pooled row.
    // 224 threads: pixel p = t/4, quarter q = t%4 (16 float4 each).
    if (tid < 224) {
        const int p = tid >> 2;
        const int q = tid & 3;
        const int base = p * 64 + q * 16;
        float s = 0.0f, m = -3.4e38f;
        #pragma unroll
        for (int i = 0; i < 16; i++) {
            const float4 v = xrow[base + i];
            s += v.x + v.y + v.z + v.w;
            m = fmaxf(m, fmaxf(fmaxf(v.x, v.y), fmaxf(v.z, v.w)));
        }
        // combine across the 4 lanes of the group (consecutive lanes, same warp)
        s += __shfl_xor_sync(0xffffffffu, s, 1);
        m  = fmaxf(m, __shfl_xor_sync(0xffffffffu, m, 1));
        s += __shfl_xor_sync(0xffffffffu, s, 2);
        m  = fmaxf(m, __shfl_xor_sync(0xffffffffu, m, 2));
        if (q == 0) {
            g_pooled[bh * W_ + p] = make_float2(s * (1.0f / C_), m);
            __threadfence();   // make pooled row visible GPU-wide before flag
        }
    }
    __syncthreads();
    if (tid == 0) {
        atomicExch(&g_flag[bh], 1);   // release: row bh pooled & published
    }

    // ---- Phase 3: wait for neighbor rows' pooled data (rows h-3..h+3, same b)
    if (tid < 7) {
        const int r = h + tid - 3;
        if (r >= 0 && r < H_) {
            volatile int* fp = &g_flag[b * H_ + r];
            while (*fp == 0) { __nanosleep(40); }
            __threadfence();  // acquire
        }
    }
    __syncthreads();

    // ---- Phase 4: gather 7x56 pooled halo (tiny, L2-hot)
    for (int i = tid; i < 7 * W_; i += 256) {
        const int kr  = i / W_;
        const int col = i - kr * W_;
        const int row = h + kr - 3;
        float2 pv = make_float2(0.0f, 0.0f);
        if (row >= 0 && row < H_) pv = g_pooled[(b * H_ + row) * W_ + col];
        pool7[kr * W_ + col] = pv;
    }
    __syncthreads();

    // ---- Phase 5: 7x7 conv (2->1 ch) + sigmoid for the 56 pixels of this row
    if (tid < W_) {
        float acc = conv_b[0];
        #pragma unroll
        for (int kh = 0; kh < 7; kh++) {
            const int row = h + kh - 3;
            if (row < 0 || row >= H_) continue;
            #pragma unroll
            for (int kw = 0; kw < 7; kw++) {
                const int col = tid + kw - 3;
                if (col < 0 || col >= W_) continue;
                const float2 pv = pool7[kh * W_ + col];
                acc = fmaf(pv.x, s_w[(kh * 7 + kw) * 2],     acc);
                acc = fmaf(pv.y, s_w[(kh * 7 + kw) * 2 + 1], acc);
            }
        }
        s_attn[tid] = 1.0f / (1.0f + expf(-acc));
    }
    __syncthreads();

    // ---- Phase 6: signal consumption of neighbor rows (for in-launch reset)
    if (tid < 7) {
        const int r = h + tid - 3;
        if (r >= 0 && r < H_) atomicAdd(&g_done[b * H_ + r], 1);
    }

    // ---- Phase 7: scale SMEM row by attn, stream out
    float4* __restrict__ o4 = reinterpret_cast<float4*>(out) + row_base4;
    #pragma unroll
    for (int it = 0; it < 14; it++) {
        const int idx = it * 256 + tid;
        const float a = s_attn[idx >> 6];
        float4 v = xrow[idx];
        v.x *= a; v.y *= a; v.z *= a; v.w *= a;
        __stcs(&o4[idx], v);
    }

    // ---- Phase 8: designated reset of this row's flag/done (leaves state
    //      zeroed for the next graph replay).
    if (tid == 0) {
        const int lo = (h - 3 < 0) ? 0 : h - 3;
        const int hi = (h + 3 > H_ - 1) ? H_ - 1 : h + 3;
        const int n_cons = hi - lo + 1;
        volatile int* dp = &g_done[bh];
        while (*dp != n_cons) { __nanosleep(40); }
        atomicExch(&g_done[bh], 0);
        atomicExch(&g_flag[bh], 0);
    }
}

extern "C" void kernel_launch(void* const* d_in, const int* in_sizes, int n_in,
                              void* d_out, int out_size) {
    const float* x      = (const float*)d_in[0];
    const float* conv_w = (const float*)d_in[1];
    const float* conv_b = (const float*)d_in[2];
    float* out          = (float*)d_out;

    cudaFuncSetAttribute(fused_kernel,
                         cudaFuncAttributeMaxDynamicSharedMemorySize, SMEM_BYTES);

    fused_kernel<<<NROWS, 256, SMEM_BYTES>>>(x, conv_w, conv_b, out);
}

// round 12
// speedup vs baseline: 1.4351x; 1.4351x over previous
#include <cuda_runtime.h>
#include <math.h>

#define B_  32
#define H_  56
#define W_  56
#define C_  256
#define NROWS (B_ * H_)          // 1792
#define ROW_F4 (W_ * C_ / 4)     // 3584 float4 per row

// Cross-CTA handshake state. Flags compare against a per-launch epoch, so no
// in-launch reset is ever needed (values only grow).
__device__ float2 g_pooled[NROWS * W_];
__device__ int    g_flag[NROWS];     // zero-init; holds epoch of last publish
__device__ int    g_epoch;           // zero-init; bumped once per launch

__global__ void epoch_kernel() {
    g_epoch += 1;
}

__global__ __launch_bounds__(256) void fused_kernel(
    const float* __restrict__ x,
    const float* __restrict__ conv_w,   // [7][7][2] HWIO
    const float* __restrict__ conv_b,   // [1]
    float* __restrict__ out)
{
    __shared__ float2 pool7[7 * W_];   // halo rows h-3..h+3
    __shared__ float  s_attn[W_];
    __shared__ float  s_w[98];
    __shared__ int    s_epoch;

    const int tid  = threadIdx.x;
    const int warp = tid >> 5;
    const int lane = tid & 31;
    const int bh   = blockIdx.x;       // b*H_ + h
    const int b    = bh / H_;
    const int h    = bh % H_;

    if (tid == 0) s_epoch = *(volatile int*)&g_epoch;
    if (tid < 98) s_w[tid] = conv_w[tid];

    const size_t row_base4 = (size_t)bh * ROW_F4;
    const float4* __restrict__ x4 = reinterpret_cast<const float4*>(x) + row_base4;

    // ---- Phase 1: pool this row from global (x's ONLY DRAM read).
    // Warp w handles pixels w, w+8, ..., w+48. Per pixel: 2 coalesced 512B loads.
    #pragma unroll
    for (int i = 0; i < 7; i++) {
        const int p = warp + 8 * i;          // 0..55
        const float4 a  = x4[p * 64 + lane];
        const float4 bv = x4[p * 64 + 32 + lane];
        float s = a.x + a.y + a.z + a.w + bv.x + bv.y + bv.z + bv.w;
        float m = fmaxf(fmaxf(fmaxf(a.x, a.y), fmaxf(a.z, a.w)),
                        fmaxf(fmaxf(bv.x, bv.y), fmaxf(bv.z, bv.w)));
        #pragma unroll
        for (int off = 16; off > 0; off >>= 1) {
            s += __shfl_xor_sync(0xffffffffu, s, off);
            m  = fmaxf(m, __shfl_xor_sync(0xffffffffu, m, off));
        }
        if (lane == 0) {
            g_pooled[bh * W_ + p] = make_float2(s * (1.0f / C_), m);
        }
    }
    __threadfence();                       // pooled row visible GPU-wide
    __syncthreads();
    const int epoch = s_epoch;
    if (tid == 0) atomicExch(&g_flag[bh], epoch);   // release

    // ---- Phase 2: wait for neighbor rows (h-3..h+3, same image).
    if (tid < 7) {
        const int r = h + tid - 3;
        if (r >= 0 && r < H_) {
            volatile int* fp = &g_flag[b * H_ + r];
            while (*fp != epoch) { __nanosleep(32); }
            __threadfence();               // acquire
        }
    }
    __syncthreads();

    // ---- Phase 3: gather 7x56 pooled halo (L2-hot, tiny).
    for (int i = tid; i < 7 * W_; i += 256) {
        const int kr  = i / W_;
        const int col = i - kr * W_;
        const int row = h + kr - 3;
        float2 pv = make_float2(0.0f, 0.0f);
        if (row >= 0 && row < H_) pv = g_pooled[(b * H_ + row) * W_ + col];
        pool7[kr * W_ + col] = pv;
    }
    __syncthreads();

    // ---- Phase 4: 7x7 conv (2->1) + sigmoid for this row's 56 pixels.
    if (tid < W_) {
        float acc = conv_b[0];
        #pragma unroll
        for (int kh = 0; kh < 7; kh++) {
            const int row = h + kh - 3;
            if (row < 0 || row >= H_) continue;
            #pragma unroll
            for (int kw = 0; kw < 7; kw++) {
                const int col = tid + kw - 3;
                if (col < 0 || col >= W_) continue;
                const float2 pv = pool7[kh * W_ + col];
                acc = fmaf(pv.x, s_w[(kh * 7 + kw) * 2],     acc);
                acc = fmaf(pv.y, s_w[(kh * 7 + kw) * 2 + 1], acc);
            }
        }
        s_attn[tid] = 1.0f / (1.0f + expf(-acc));
    }
    __syncthreads();

    // ---- Phase 5: scale. Second x read hits L2 (read µs ago); stream out.
    float4* __restrict__ o4 = reinterpret_cast<float4*>(out) + row_base4;
    #pragma unroll
    for (int it = 0; it < 14; it++) {
        const int idx = it * 256 + tid;
        const float a = s_attn[idx >> 6];
        float4 v = x4[idx];
        v.x *= a; v.y *= a; v.z *= a; v.w *= a;
        __stcs(&o4[idx], v);
    }
}

extern "C" void kernel_launch(void* const* d_in, const int* in_sizes, int n_in,
                              void* d_out, int out_size) {
    const float* x      = (const float*)d_in[0];
    const float* conv_w = (const float*)d_in[1];
    const float* conv_b = (const float*)d_in[2];
    float* out          = (float*)d_out;

    epoch_kernel<<<1, 1>>>();
    fused_kernel<<<NROWS, 256>>>(x, conv_w, conv_b, out);
}

// round 15
// speedup vs baseline: 1.5608x; 1.0876x over previous
#include <cuda_runtime.h>
#include <math.h>

#define B_  32
#define H_  56
#define W_  56
#define C_  256
#define NROWS (B_ * H_)          // 1792
#define ROW_F4 (W_ * C_ / 4)     // 3584 float4 per row
#define GRID_  (NROWS / 2)       // 896  -> exactly one wave, 2 rows per CTA

// Cross-CTA handshake. Flags are monotonically increasing "publish counters":
// after launch n completes, every flag == n. A CTA learns the current epoch by
// reading its OWN row's flag (only it ever writes that slot), publishes E+1,
// and waits for neighbors to reach E+1. No reset, no helper kernel.
__device__ float2 g_pooled[NROWS * W_];
__device__ int    g_flag[NROWS];     // zero-initialized

__global__ __launch_bounds__(256) void fused_kernel(
    const float* __restrict__ x,
    const float* __restrict__ conv_w,   // [7][7][2] HWIO
    const float* __restrict__ conv_b,   // [1]
    float* __restrict__ out)
{
    __shared__ float2 pool7[7 * W_];   // halo rows h-3..h+3
    __shared__ float  s_attn[W_];
    __shared__ float  s_w[98];

    const int tid  = threadIdx.x;
    const int warp = tid >> 5;
    const int lane = tid & 31;

    if (tid < 98) s_w[tid] = conv_w[tid];

    // Current epoch: read our own row's flag (race-free; launches serialize).
    const int E = *(volatile int*)&g_flag[blockIdx.x];

    #pragma unroll
    for (int rr = 0; rr < 2; rr++) {
        const int bh = blockIdx.x + rr * GRID_;   // row index, < NROWS
        const int b  = bh / H_;
        const int h  = bh % H_;

        const size_t row_base4 = (size_t)bh * ROW_F4;
        const float4* __restrict__ x4 =
            reinterpret_cast<const float4*>(x) + row_base4;

        // ---- Phase 1: channel avg/max pool for this row (x read #1).
        // Warp w handles pixels w, w+8, ..., w+48: two coalesced 512B loads each.
        #pragma unroll
        for (int i = 0; i < 7; i++) {
            const int p = warp + 8 * i;            // 0..55
            const float4 a  = x4[p * 64 + lane];
            const float4 bv = x4[p * 64 + 32 + lane];
            float s = a.x + a.y + a.z + a.w + bv.x + bv.y + bv.z + bv.w;
            float m = fmaxf(fmaxf(fmaxf(a.x, a.y), fmaxf(a.z, a.w)),
                            fmaxf(fmaxf(bv.x, bv.y), fmaxf(bv.z, bv.w)));
            #pragma unroll
            for (int off = 16; off > 0; off >>= 1) {
                s += __shfl_xor_sync(0xffffffffu, s, off);
                m  = fmaxf(m, __shfl_xor_sync(0xffffffffu, m, off));
            }
            if (lane == 0) {
                g_pooled[bh * W_ + p] = make_float2(s * (1.0f / C_), m);
            }
        }
        __threadfence();                           // pooled row visible GPU-wide
        __syncthreads();
        if (tid == 0) atomicExch(&g_flag[bh], E + 1);   // release-publish

        // ---- Phase 2: wait for neighbor rows (h-3..h+3, same image).
        if (tid < 7) {
            const int r = h + tid - 3;
            if (r >= 0 && r < H_) {
                volatile int* fp = &g_flag[b * H_ + r];
                while (*fp <= E) { __nanosleep(32); }
                __threadfence();                   // acquire
            }
        }
        __syncthreads();

        // ---- Phase 3: gather 7x56 pooled halo (tiny, L2-hot).
        for (int i = tid; i < 7 * W_; i += 256) {
            const int kr  = i / W_;
            const int col = i - kr * W_;
            const int row = h + kr - 3;
            float2 pv = make_float2(0.0f, 0.0f);
            if (row >= 0 && row < H_) pv = g_pooled[(b * H_ + row) * W_ + col];
            pool7[kr * W_ + col] = pv;
        }
        __syncthreads();

        // ---- Phase 4: 7x7 conv (2->1) + sigmoid for this row's 56 pixels.
        if (tid < W_) {
            float acc = conv_b[0];
            #pragma unroll
            for (int kh = 0; kh < 7; kh++) {
                const int row = h + kh - 3;
                if (row < 0 || row >= H_) continue;
                #pragma unroll
                for (int kw = 0; kw < 7; kw++) {
                    const int col = tid + kw - 3;
                    if (col < 0 || col >= W_) continue;
                    const float2 pv = pool7[kh * W_ + col];
                    acc = fmaf(pv.x, s_w[(kh * 7 + kw) * 2],     acc);
                    acc = fmaf(pv.y, s_w[(kh * 7 + kw) * 2 + 1], acc);
                }
            }
            s_attn[tid] = 1.0f / (1.0f + expf(-acc));
        }
        __syncthreads();

        // ---- Phase 5: scale (x read #2, L2-hot: read ~50 MB of chip work ago)
        float4* __restrict__ o4 = reinterpret_cast<float4*>(out) + row_base4;
        #pragma unroll
        for (int it = 0; it < 14; it++) {
            const int idx = it * 256 + tid;
            const float a = s_attn[idx >> 6];
            float4 v = x4[idx];
            v.x *= a; v.y *= a; v.z *= a; v.w *= a;
            __stcs(&o4[idx], v);
        }
        __syncthreads();   // protect s_attn/pool7 before next iteration
    }
}

extern "C" void kernel_launch(void* const* d_in, const int* in_sizes, int n_in,
                              void* d_out, int out_size) {
    const float* x      = (const float*)d_in[0];
    const float* conv_w = (const float*)d_in[1];
    const float* conv_b = (const float*)d_in[2];
    float* out          = (float*)d_out;

    fused_kernel<<<GRID_, 256>>>(x, conv_w, conv_b, out);
}